// round 10
// baseline (speedup 1.0000x reference)
#include <cuda_runtime.h>
#include <cuda_bf16.h>
#include <cstdint>

// Problem constants
constexpr int B_ = 256;   // batch
constexpr int T_ = 128;   // trees
constexpr int N_ = 256;   // nodes (= classes)
constexpr int E_ = 64;    // embedding
constexpr int H_ = 16;    // hidden
constexpr int K2_ = (T_ - 1) * H_;  // 2032

// Scratch (device global; no runtime allocation)
__device__ __nv_bfloat16 g_be[T_ * B_ * E_];  // [j][b][e] bf16, 4 MB

// ---------------------------------------------------------------------------
// Kernel 1: gather embeddings (shifted index) -> bf16 [j][b][e]
// ---------------------------------------------------------------------------
__global__ void gather_bf16_kernel(const int* __restrict__ x,
                                   const float* __restrict__ emb) {
    int j    = blockIdx.x;
    int b    = blockIdx.y * 64 + (threadIdx.x >> 1);
    int half = threadIdx.x & 1;
    int row  = x[b * T_ + j] + j * N_;
    const float4* src =
        reinterpret_cast<const float4*>(emb + (size_t)row * E_ + half * 32);
    __nv_bfloat162 v[16];
#pragma unroll
    for (int k = 0; k < 8; ++k) {
        float4 f = src[k];
        v[2 * k + 0] = __floats2bfloat162_rn(f.x, f.y);
        v[2 * k + 1] = __floats2bfloat162_rn(f.z, f.w);
    }
    uint4* dst = reinterpret_cast<uint4*>(
        g_be + ((size_t)j * B_ + b) * E_ + half * 32);
    const uint4* vp = reinterpret_cast<const uint4*>(v);
#pragma unroll
    for (int k = 0; k < 4; ++k) dst[k] = vp[k];
}

// ---------------------------------------------------------------------------
// mma.sync m16n8k16 bf16 (fp32 accum) + ldmatrix helpers
// ---------------------------------------------------------------------------
__device__ __forceinline__ void mma_bf16(float* c, const uint32_t* a,
                                         uint32_t b0, uint32_t b1) {
    asm volatile(
        "mma.sync.aligned.m16n8k16.row.col.f32.bf16.bf16.f32 "
        "{%0,%1,%2,%3}, {%4,%5,%6,%7}, {%8,%9}, {%0,%1,%2,%3};"
        : "+f"(c[0]), "+f"(c[1]), "+f"(c[2]), "+f"(c[3])
        : "r"(a[0]), "r"(a[1]), "r"(a[2]), "r"(a[3]), "r"(b0), "r"(b1));
}

#define LDSM_X4(r0, r1, r2, r3, addr)                                     \
    asm volatile("ldmatrix.sync.aligned.m8n8.x4.shared.b16 "              \
                 "{%0,%1,%2,%3}, [%4];"                                   \
                 : "=r"(r0), "=r"(r1), "=r"(r2), "=r"(r3) : "r"(addr))

#define CP_ASYNC16(dst, src)                                         \
    asm volatile("cp.async.cg.shared.global [%0], [%1], 16;" ::      \
                 "r"(dst), "l"(src))
#define CP_COMMIT() asm volatile("cp.async.commit_group;" ::: "memory")
#define CP_WAIT1()  asm volatile("cp.async.wait_group 1;" ::: "memory")
#define CP_WAIT0()  asm volatile("cp.async.wait_group 0;" ::: "memory")

// Fused-kernel SMEM layout (bytes) -- per-CTA tile is 128 batch rows
constexpr int BE_STRIDE = 144;              // 64 bf16 + 8 pad (conflict-free)
constexpr int BE_BUF    = 128 * BE_STRIDE;  // 18432 (128 batch rows)
constexpr int W1_STRIDE = 144;              // [h][e] bf16
constexpr int W1_BUF    = 16 * W1_STRIDE;   // 2304
constexpr int W2_STRIDE = 48;               // [e][h] bf16
constexpr int W2_BUF    = 64 * W2_STRIDE;   // 3072
constexpr int OFF_BE = 0;                            // 3 bufs = 55296
constexpr int OFF_W1 = OFF_BE + 3 * BE_BUF;          // 55296
constexpr int OFF_W2 = OFF_W1 + 2 * W1_BUF;          // 59904
constexpr int OFF_B1 = OFF_W2 + 2 * W2_BUF;          // 66048
constexpr int OFF_B2 = OFF_B1 + T_ * H_ * 4;         // 74240
constexpr int SMEM_TOTAL = OFF_B2 + E_ * 4;          // 74496  (x2 CTA = 149KB)
// W3 bf16 [n][e] staging (256 rows x 144B = 36864) overlays dead BE ring
constexpr int OFF_W3S = 0;

// ---------------------------------------------------------------------------
// Kernel 2: fully fused stages 2..7. grid (2,128): h = batch half, i = tree.
// 256 threads = 8 warps, warp w owns batch rows h*128 + [16w,16w+16).
// 2 CTAs/SM -> independent barrier domains hide each other's stalls.
// ---------------------------------------------------------------------------
__global__ void __launch_bounds__(256, 2)
fused_all_kernel(const float* __restrict__ lin1,   // [T,T,E,H]
                 const float* __restrict__ b1,     // [T,T,H]
                 const float* __restrict__ lin2,   // [T,(T-1)*H,E]
                 const float* __restrict__ b2,     // [T,E]
                 const float* __restrict__ w3g,    // [T,E,N]
                 const int*   __restrict__ x,      // [B,T]
                 float* __restrict__ out) {        // [B,T]
    extern __shared__ char smem[];
    const int h    = blockIdx.x;
    const int i    = blockIdx.y;
    const int tid  = threadIdx.x;
    const int w    = tid >> 5;
    const int lane = tid & 31;
    const int q    = lane & 3;
    const int r4   = lane >> 2;

    float* sb1 = reinterpret_cast<float*>(smem + OFF_B1);
    float* sb2 = reinterpret_cast<float*>(smem + OFF_B2);
    const uint32_t smem_u32 = (uint32_t)__cvta_generic_to_shared(smem);

    // ldmatrix lane-dependent base offsets (hoisted):
    const uint32_t a_off = smem_u32 + OFF_BE +
        (w * 16 + (lane & 15)) * BE_STRIDE + (lane >> 4) * 16;
    const int brow = (lane & 7) + ((lane >> 1) & 8);
    const int bcol = ((lane >> 3) & 1) * 16;
    const uint32_t w1_off = smem_u32 + OFF_W1 + brow * W1_STRIDE + bcol;
    const uint32_t w2_off = smem_u32 + OFF_W2 + brow * W2_STRIDE + bcol;
    const uint32_t w3_off = smem_u32 + OFF_W3S + brow * 144 + bcol;

    auto jof = [&](int jj) { return jj + (jj >= i); };

    auto stage_be = [&](int buf, int j) {
        uint32_t dst0 = smem_u32 + OFF_BE + buf * BE_BUF;
        const char* src = reinterpret_cast<const char*>(
            g_be + ((size_t)j * B_ + h * 128) * E_);
#pragma unroll
        for (int u = 0; u < 4; ++u) {
            int c = tid + 256 * u;             // 1024 x 16B chunks
            int row = c >> 3, off = c & 7;
            CP_ASYNC16(dst0 + row * BE_STRIDE + off * 16, src + c * 16);
        }
    };

    struct WRegs { float4 v1, v2; };
    auto ldg_w = [&](int j) {
        WRegs r;
        r.v1 = reinterpret_cast<const float4*>(
            lin1 + (size_t)(i * T_ + j) * (E_ * H_))[tid];
        int kk = (j < i) ? j : j - 1;
        r.v2 = reinterpret_cast<const float4*>(
            lin2 + ((size_t)i * K2_ + (size_t)kk * H_) * E_)[tid];
        return r;
    };
    auto sts_w = [&](int buf, const WRegs& r) {
        __nv_bfloat16* w1 =
            reinterpret_cast<__nv_bfloat16*>(smem + OFF_W1 + buf * W1_BUF);
        {
            int idx = tid * 4;
            const float* f = reinterpret_cast<const float*>(&r.v1);
#pragma unroll
            for (int s = 0; s < 4; ++s) {
                int e = (idx + s) >> 4, hh = (idx + s) & 15;
                w1[hh * (W1_STRIDE / 2) + e] = __float2bfloat16(f[s]);
            }
        }
        __nv_bfloat16* w2 =
            reinterpret_cast<__nv_bfloat16*>(smem + OFF_W2 + buf * W2_BUF);
        {
            int idx = tid * 4;
            const float* f = reinterpret_cast<const float*>(&r.v2);
#pragma unroll
            for (int s = 0; s < 4; ++s) {
                int k = (idx + s) >> 6, e = (idx + s) & 63;
                w2[e * (W2_STRIDE / 2) + k] = __float2bfloat16(f[s]);
            }
        }
    };

    // ---- prologue ----------------------------------------------------------
#pragma unroll
    for (int u = 0; u < 8; ++u)
        sb1[tid + 256 * u] = b1[(size_t)i * T_ * H_ + tid + 256 * u];
    if (tid < E_) sb2[tid] = b2[(size_t)i * E_ + tid];

    stage_be(0, jof(0)); CP_COMMIT();
    WRegs w0 = ldg_w(jof(0));
    sts_w(0, w0);
    stage_be(1, jof(1)); CP_COMMIT();
    WRegs wr = ldg_w(jof(1));              // invariant: wr = W(jj+1)

    float zacc[8][4];
#pragma unroll
    for (int nt = 0; nt < 8; ++nt)
#pragma unroll
        for (int s = 0; s < 4; ++s) zacc[nt][s] = 0.f;

    // ---- main loop over jj (j != i) ---------------------------------------
    for (int jj = 0; jj < T_ - 1; ++jj) {
        const int j = jof(jj);

        CP_WAIT1();              // BE(jj) complete
        __syncthreads();

        if (jj + 1 < T_ - 1) sts_w((jj + 1) & 1, wr);
        if (jj + 2 < T_ - 1) {
            wr = ldg_w(jof(jj + 2));
            stage_be((jj + 2) % 3, jof(jj + 2));
        }
        CP_COMMIT();             // one group per iteration (maybe empty)

        const uint32_t beb = a_off  + (jj % 3) * BE_BUF;
        const uint32_t w1b = w1_off + (jj & 1) * W1_BUF;
        const uint32_t w2b = w2_off + (jj & 1) * W2_BUF;

        // A-fragments: 4x ldmatrix.x4 (m16k64 strip)
        uint32_t a[4][4];
#pragma unroll
        for (int kt = 0; kt < 4; ++kt)
            LDSM_X4(a[kt][0], a[kt][1], a[kt][2], a[kt][3], beb + kt * 32);

        // GEMM1: tmp[16,16] = BE[16,64] @ W1[64,16] (+bias1)
        float c1[2][4];
#pragma unroll
        for (int nt = 0; nt < 2; ++nt) {
            float bv0 = sb1[j * H_ + nt * 8 + 2 * q];
            float bv1 = sb1[j * H_ + nt * 8 + 2 * q + 1];
            c1[nt][0] = bv0; c1[nt][1] = bv1;
            c1[nt][2] = bv0; c1[nt][3] = bv1;
        }
#pragma unroll
        for (int kt = 0; kt < 4; ++kt) {
            uint32_t b0, b1r, b2r, b3;
            LDSM_X4(b0, b1r, b2r, b3, w1b + kt * 32);
            mma_bf16(c1[0], a[kt], b0, b1r);
            mma_bf16(c1[1], a[kt], b2r, b3);
        }

        // relu + cvt C-frags -> GEMM2 A-frag (registers only)
#pragma unroll
        for (int nt = 0; nt < 2; ++nt)
#pragma unroll
            for (int s = 0; s < 4; ++s) c1[nt][s] = fmaxf(c1[nt][s], 0.f);
        uint32_t a2[4];
        {
            __nv_bfloat162 p0 = __floats2bfloat162_rn(c1[0][0], c1[0][1]);
            __nv_bfloat162 p1 = __floats2bfloat162_rn(c1[0][2], c1[0][3]);
            __nv_bfloat162 p2 = __floats2bfloat162_rn(c1[1][0], c1[1][1]);
            __nv_bfloat162 p3 = __floats2bfloat162_rn(c1[1][2], c1[1][3]);
            a2[0] = *reinterpret_cast<uint32_t*>(&p0);
            a2[1] = *reinterpret_cast<uint32_t*>(&p1);
            a2[2] = *reinterpret_cast<uint32_t*>(&p2);
            a2[3] = *reinterpret_cast<uint32_t*>(&p3);
        }

        // GEMM2: z[16,64] += tmp[16,16] @ W2[16,64]
#pragma unroll
        for (int p = 0; p < 4; ++p) {
            uint32_t b0, b1r, b2r, b3;
            LDSM_X4(b0, b1r, b2r, b3, w2b + p * 16 * W2_STRIDE);
            mma_bf16(zacc[2 * p + 0], a2, b0, b1r);
            mma_bf16(zacc[2 * p + 1], a2, b2r, b3);
        }
    }

    // ======================= fused CE head ==================================
    CP_WAIT0();
    __syncthreads();             // BE ring dead; reuse as W3 staging

    // W3[i] fp32 [e][n] -> smem bf16 [n][e] (rows 144B)
    {
        const float4* w3p =
            reinterpret_cast<const float4*>(w3g + (size_t)i * E_ * N_);
        __nv_bfloat16* W3S = reinterpret_cast<__nv_bfloat16*>(smem + OFF_W3S);
#pragma unroll
        for (int it = 0; it < 16; ++it) {
            int idx = it * 256 + tid;          // 4096 float4 total
            float4 f = w3p[idx];
            int e = idx >> 6, n0 = (idx & 63) * 4;
            W3S[(n0 + 0) * 72 + e] = __float2bfloat16(f.x);
            W3S[(n0 + 1) * 72 + e] = __float2bfloat16(f.y);
            W3S[(n0 + 2) * 72 + e] = __float2bfloat16(f.z);
            W3S[(n0 + 3) * 72 + e] = __float2bfloat16(f.w);
        }
    }

    // z + bias2 -> bf16 A-fragments
    uint32_t az[4][4];
#pragma unroll
    for (int kt = 0; kt < 4; ++kt) {
        float v[2][4];
#pragma unroll
        for (int p = 0; p < 2; ++p) {
            int nt = 2 * kt + p;
            float bx = sb2[nt * 8 + 2 * q], by = sb2[nt * 8 + 2 * q + 1];
            v[p][0] = zacc[nt][0] + bx; v[p][1] = zacc[nt][1] + by;
            v[p][2] = zacc[nt][2] + bx; v[p][3] = zacc[nt][3] + by;
        }
        __nv_bfloat162 p0 = __floats2bfloat162_rn(v[0][0], v[0][1]);
        __nv_bfloat162 p1 = __floats2bfloat162_rn(v[0][2], v[0][3]);
        __nv_bfloat162 p2 = __floats2bfloat162_rn(v[1][0], v[1][1]);
        __nv_bfloat162 p3 = __floats2bfloat162_rn(v[1][2], v[1][3]);
        az[kt][0] = *reinterpret_cast<uint32_t*>(&p0);
        az[kt][1] = *reinterpret_cast<uint32_t*>(&p1);
        az[kt][2] = *reinterpret_cast<uint32_t*>(&p2);
        az[kt][3] = *reinterpret_cast<uint32_t*>(&p3);
    }

    int xv[2];
    xv[0] = x[(size_t)(h * 128 + w * 16 + r4) * T_ + i];
    xv[1] = x[(size_t)(h * 128 + w * 16 + r4 + 8) * T_ + i];

    __syncthreads();             // W3S ready

    float sum[2] = {0.f, 0.f};
    float picked[2] = {0.f, 0.f};

#pragma unroll
    for (int n0 = 0; n0 < 4; ++n0) {           // 64 classes per chunk
        float c[8][4];
#pragma unroll
        for (int nt = 0; nt < 8; ++nt)
#pragma unroll
            for (int s = 0; s < 4; ++s) c[nt][s] = 0.f;
#pragma unroll
        for (int ntp = 0; ntp < 4; ++ntp) {
#pragma unroll
            for (int kt = 0; kt < 4; ++kt) {
                uint32_t b0, b1r, b2r, b3;
                LDSM_X4(b0, b1r, b2r, b3,
                        w3_off + (n0 * 64 + ntp * 16) * 144 + kt * 32);
                mma_bf16(c[2 * ntp + 0], az[kt], b0, b1r);
                mma_bf16(c[2 * ntp + 1], az[kt], b2r, b3);
            }
        }
#pragma unroll
        for (int nt = 0; nt < 8; ++nt)
#pragma unroll
            for (int s = 0; s < 4; ++s) {
                int n = n0 * 64 + nt * 8 + 2 * q + (s & 1);
                int hh = s >> 1;
                float v = c[nt][s];
                sum[hh] += __expf(v);
                if (n == xv[hh]) picked[hh] = v;
            }
    }

    // reduce over the 4 q-lanes (consecutive lanes r4*4+q)
#pragma unroll
    for (int hh = 0; hh < 2; ++hh) {
        float s = sum[hh], p = picked[hh];
        s += __shfl_xor_sync(0xffffffffu, s, 1);
        s += __shfl_xor_sync(0xffffffffu, s, 2);
        p += __shfl_xor_sync(0xffffffffu, p, 1);
        p += __shfl_xor_sync(0xffffffffu, p, 2);
        if (q == 0) {
            int row = h * 128 + w * 16 + r4 + 8 * hh;
            out[(size_t)row * T_ + i] = __logf(s) - p;
        }
    }
}

// ---------------------------------------------------------------------------
extern "C" void kernel_launch(void* const* d_in, const int* in_sizes, int n_in,
                              void* d_out, int out_size) {
    const int*   x    = (const int*)  d_in[0];  // [B,T]
    const float* emb  = (const float*)d_in[1];  // [N*T,E]
    const float* lin1 = (const float*)d_in[2];  // [T,T,E,H]
    const float* b1   = (const float*)d_in[3];  // [T,T,H]
    const float* lin2 = (const float*)d_in[4];  // [T,(T-1)*H,E]
    const float* b2   = (const float*)d_in[5];  // [T,E]
    const float* w3   = (const float*)d_in[6];  // [T,E,N]
    float* out = (float*)d_out;                 // [B,T]

    cudaFuncSetAttribute(fused_all_kernel,
                         cudaFuncAttributeMaxDynamicSharedMemorySize,
                         SMEM_TOTAL);

    gather_bf16_kernel<<<dim3(T_, B_ / 64), 128>>>(x, emb);
    fused_all_kernel<<<dim3(2, T_), 256, SMEM_TOTAL>>>(lin1, b1, lin2, b2,
                                                       w3, x, out);
}

// round 12
// speedup vs baseline: 1.0577x; 1.0577x over previous
#include <cuda_runtime.h>
#include <cuda_bf16.h>
#include <cstdint>

// Problem constants
constexpr int B_ = 256;   // batch
constexpr int T_ = 128;   // trees
constexpr int N_ = 256;   // nodes (= classes)
constexpr int E_ = 64;    // embedding
constexpr int H_ = 16;    // hidden
constexpr int K2_ = (T_ - 1) * H_;  // 2032

// Scratch (device global; no runtime allocation)
__device__ __nv_bfloat16 g_be[T_ * B_ * E_];  // [j][b][e] bf16, 4 MB

// ---------------------------------------------------------------------------
// Kernel 1: gather embeddings (shifted index) -> bf16 [j][b][e]
// ---------------------------------------------------------------------------
__global__ void gather_bf16_kernel(const int* __restrict__ x,
                                   const float* __restrict__ emb) {
    int j    = blockIdx.x;
    int b    = blockIdx.y * 64 + (threadIdx.x >> 1);
    int half = threadIdx.x & 1;
    int row  = x[b * T_ + j] + j * N_;
    const float4* src =
        reinterpret_cast<const float4*>(emb + (size_t)row * E_ + half * 32);
    __nv_bfloat162 v[16];
#pragma unroll
    for (int k = 0; k < 8; ++k) {
        float4 f = src[k];
        v[2 * k + 0] = __floats2bfloat162_rn(f.x, f.y);
        v[2 * k + 1] = __floats2bfloat162_rn(f.z, f.w);
    }
    uint4* dst = reinterpret_cast<uint4*>(
        g_be + ((size_t)j * B_ + b) * E_ + half * 32);
    const uint4* vp = reinterpret_cast<const uint4*>(v);
#pragma unroll
    for (int k = 0; k < 4; ++k) dst[k] = vp[k];
}

// ---------------------------------------------------------------------------
// mma.sync m16n8k16 bf16 (fp32 accum) + ldmatrix helpers
// ---------------------------------------------------------------------------
__device__ __forceinline__ void mma_bf16(float* c, const uint32_t* a,
                                         uint32_t b0, uint32_t b1) {
    asm volatile(
        "mma.sync.aligned.m16n8k16.row.col.f32.bf16.bf16.f32 "
        "{%0,%1,%2,%3}, {%4,%5,%6,%7}, {%8,%9}, {%0,%1,%2,%3};"
        : "+f"(c[0]), "+f"(c[1]), "+f"(c[2]), "+f"(c[3])
        : "r"(a[0]), "r"(a[1]), "r"(a[2]), "r"(a[3]), "r"(b0), "r"(b1));
}

#define LDSM_X4(r0, r1, r2, r3, addr)                                     \
    asm volatile("ldmatrix.sync.aligned.m8n8.x4.shared.b16 "              \
                 "{%0,%1,%2,%3}, [%4];"                                   \
                 : "=r"(r0), "=r"(r1), "=r"(r2), "=r"(r3) : "r"(addr))

#define CP_ASYNC16(dst, src)                                         \
    asm volatile("cp.async.cg.shared.global [%0], [%1], 16;" ::      \
                 "r"(dst), "l"(src))
#define CP_COMMIT() asm volatile("cp.async.commit_group;" ::: "memory")
#define CP_WAIT0()  asm volatile("cp.async.wait_group 0;" ::: "memory")

// Fused-kernel SMEM layout (bytes)
constexpr int BE_STRIDE = 144;              // 64 bf16 + 8 pad (conflict-free)
constexpr int BE_BUF    = 256 * BE_STRIDE;  // 36864 (256 batch rows)
constexpr int W1_STRIDE = 144;              // [h][e] bf16
constexpr int W1_BUF    = 16 * W1_STRIDE;   // 2304
constexpr int W2_STRIDE = 48;               // [e][h] bf16
constexpr int W2_BUF    = 64 * W2_STRIDE;   // 3072
constexpr int OFF_BE = 0;                            // 4 bufs = 147456
constexpr int OFF_W1 = OFF_BE + 4 * BE_BUF;          // 147456 (4 bufs)
constexpr int OFF_W2 = OFF_W1 + 4 * W1_BUF;          // 156672 (4 bufs)
constexpr int OFF_B1 = OFF_W2 + 4 * W2_BUF;          // 168960
constexpr int OFF_B2 = OFF_B1 + T_ * H_ * 4;         // 177152
constexpr int SMEM_TOTAL = OFF_B2 + E_ * 4;          // 177408
// W3 bf16 [n][e] staging overlays the dead BE ring in the epilogue
constexpr int OFF_W3S = 0;                  // 256 rows x 144B

// ---------------------------------------------------------------------------
// Kernel 2: fully fused stages 2..7. CTA = tree i, 512 threads = 16 warps,
// warp w owns batch rows [16w,16w+16). j processed in PAIRS: one barrier +
// one cp.async wait per 2 iterations; j0/j1 chains overlap (no barrier
// between). BE ring of 4 (pair prefetch depth 1), W ring of 4.
// ---------------------------------------------------------------------------
__global__ void __launch_bounds__(512, 1)
fused_all_kernel(const float* __restrict__ lin1,   // [T,T,E,H]
                 const float* __restrict__ b1,     // [T,T,H]
                 const float* __restrict__ lin2,   // [T,(T-1)*H,E]
                 const float* __restrict__ b2,     // [T,E]
                 const float* __restrict__ w3g,    // [T,E,N]
                 const int*   __restrict__ x,      // [B,T]
                 float* __restrict__ out) {        // [B,T]
    extern __shared__ char smem[];
    const int i    = blockIdx.x;
    const int tid  = threadIdx.x;
    const int w    = tid >> 5;
    const int lane = tid & 31;
    const int q    = lane & 3;
    const int r4   = lane >> 2;

    float* sb1 = reinterpret_cast<float*>(smem + OFF_B1);
    float* sb2 = reinterpret_cast<float*>(smem + OFF_B2);
    const uint32_t smem_u32 = (uint32_t)__cvta_generic_to_shared(smem);

    // ldmatrix lane-dependent base offsets (hoisted):
    const uint32_t a_off = smem_u32 + OFF_BE +
        (w * 16 + (lane & 15)) * BE_STRIDE + (lane >> 4) * 16;
    const int brow = (lane & 7) + ((lane >> 1) & 8);
    const int bcol = ((lane >> 3) & 1) * 16;
    const uint32_t w1_off = smem_u32 + OFF_W1 + brow * W1_STRIDE + bcol;
    const uint32_t w2_off = smem_u32 + OFF_W2 + brow * W2_STRIDE + bcol;
    const uint32_t w3_off = smem_u32 + OFF_W3S + brow * 144 + bcol;

    auto jof = [&](int jj) { return jj + (jj >= i); };

    auto stage_be = [&](int buf, int j) {
        uint32_t dst0 = smem_u32 + OFF_BE + buf * BE_BUF;
        const char* src =
            reinterpret_cast<const char*>(g_be + (size_t)j * B_ * E_);
#pragma unroll
        for (int u = 0; u < 4; ++u) {
            int c = tid + 512 * u;             // 2048 x 16B chunks
            int row = c >> 3, off = c & 7;
            CP_ASYNC16(dst0 + row * BE_STRIDE + off * 16, src + c * 16);
        }
    };

    struct WRegs { float2 v1, v2; };
    auto ldg_w = [&](int j) {
        WRegs r;
        r.v1 = reinterpret_cast<const float2*>(
            lin1 + (size_t)(i * T_ + j) * (E_ * H_))[tid];
        int kk = (j < i) ? j : j - 1;
        r.v2 = reinterpret_cast<const float2*>(
            lin2 + ((size_t)i * K2_ + (size_t)kk * H_) * E_)[tid];
        return r;
    };
    auto sts_w = [&](int buf, const WRegs& r) {
        __nv_bfloat16* w1 =
            reinterpret_cast<__nv_bfloat16*>(smem + OFF_W1 + buf * W1_BUF);
        {
            int idx = tid * 2;
            const float* f = reinterpret_cast<const float*>(&r.v1);
#pragma unroll
            for (int s = 0; s < 2; ++s) {
                int e = (idx + s) >> 4, hh = (idx + s) & 15;
                w1[hh * (W1_STRIDE / 2) + e] = __float2bfloat16(f[s]);
            }
        }
        __nv_bfloat16* w2 =
            reinterpret_cast<__nv_bfloat16*>(smem + OFF_W2 + buf * W2_BUF);
        {
            int idx = tid * 2;
            const float* f = reinterpret_cast<const float*>(&r.v2);
#pragma unroll
            for (int s = 0; s < 2; ++s) {
                int k = (idx + s) >> 6, e = (idx + s) & 63;
                w2[e * (W2_STRIDE / 2) + k] = __float2bfloat16(f[s]);
            }
        }
    };

    // ---- prologue ----------------------------------------------------------
#pragma unroll
    for (int u = 0; u < 4; ++u)
        sb1[tid + 512 * u] = b1[(size_t)i * T_ * H_ + tid + 512 * u];
    if (tid < E_) sb2[tid] = b2[(size_t)i * E_ + tid];

    stage_be(0, jof(0));
    stage_be(1, jof(1));
    CP_COMMIT();                              // group: pair 0
    {
        WRegs wa = ldg_w(jof(0));
        WRegs wb = ldg_w(jof(1));
        sts_w(0, wa);
        sts_w(1, wb);
    }
    WRegs wrA = ldg_w(jof(2));                // W for idx 2 (pair 1)
    WRegs wrB = ldg_w(jof(3));                // W for idx 3 (pair 1)

    float zacc[8][4];
#pragma unroll
    for (int nt = 0; nt < 8; ++nt)
#pragma unroll
        for (int s = 0; s < 4; ++s) zacc[nt][s] = 0.f;

    // one-j compute body
    auto compute_j = [&](int idx) {
        const int j   = jof(idx);
        const int buf = idx & 3;
        const uint32_t beb = a_off  + buf * BE_BUF;
        const uint32_t w1b = w1_off + buf * W1_BUF;
        const uint32_t w2b = w2_off + buf * W2_BUF;

        // A-fragments: 4x ldmatrix.x4 (m16k64 strip)
        uint32_t a[4][4];
#pragma unroll
        for (int kt = 0; kt < 4; ++kt)
            LDSM_X4(a[kt][0], a[kt][1], a[kt][2], a[kt][3], beb + kt * 32);

        // GEMM1: tmp[16,16] = BE[16,64] @ W1[64,16] (+bias1)
        float c1[2][4];
#pragma unroll
        for (int nt = 0; nt < 2; ++nt) {
            float bv0 = sb1[j * H_ + nt * 8 + 2 * q];
            float bv1 = sb1[j * H_ + nt * 8 + 2 * q + 1];
            c1[nt][0] = bv0; c1[nt][1] = bv1;
            c1[nt][2] = bv0; c1[nt][3] = bv1;
        }
#pragma unroll
        for (int kt = 0; kt < 4; ++kt) {
            uint32_t b0, b1r, b2r, b3;
            LDSM_X4(b0, b1r, b2r, b3, w1b + kt * 32);
            mma_bf16(c1[0], a[kt], b0, b1r);
            mma_bf16(c1[1], a[kt], b2r, b3);
        }

        // relu + cvt C-frags -> GEMM2 A-frag (registers only)
#pragma unroll
        for (int nt = 0; nt < 2; ++nt)
#pragma unroll
            for (int s = 0; s < 4; ++s) c1[nt][s] = fmaxf(c1[nt][s], 0.f);
        uint32_t a2[4];
        {
            __nv_bfloat162 p0 = __floats2bfloat162_rn(c1[0][0], c1[0][1]);
            __nv_bfloat162 p1 = __floats2bfloat162_rn(c1[0][2], c1[0][3]);
            __nv_bfloat162 p2 = __floats2bfloat162_rn(c1[1][0], c1[1][1]);
            __nv_bfloat162 p3 = __floats2bfloat162_rn(c1[1][2], c1[1][3]);
            a2[0] = *reinterpret_cast<uint32_t*>(&p0);
            a2[1] = *reinterpret_cast<uint32_t*>(&p1);
            a2[2] = *reinterpret_cast<uint32_t*>(&p2);
            a2[3] = *reinterpret_cast<uint32_t*>(&p3);
        }

        // GEMM2: z[16,64] += tmp[16,16] @ W2[16,64]
#pragma unroll
        for (int p = 0; p < 4; ++p) {
            uint32_t b0, b1r, b2r, b3;
            LDSM_X4(b0, b1r, b2r, b3, w2b + p * 16 * W2_STRIDE);
            mma_bf16(zacc[2 * p + 0], a2, b0, b1r);
            mma_bf16(zacc[2 * p + 1], a2, b2r, b3);
        }
    };

    // ---- main loop: 64 pairs over idx = 0..126 -----------------------------
    for (int p = 0; p < 64; ++p) {
        const int i0 = 2 * p;

        CP_WAIT0();              // this pair's BE staged
        __syncthreads();

        // stage next pair's W (bufs not in use this pair) + BE, refill W regs
        if (i0 + 2 < 127) sts_w((i0 + 2) & 3, wrA);
        if (i0 + 3 < 127) sts_w((i0 + 3) & 3, wrB);
        if (i0 + 2 < 127) stage_be((i0 + 2) & 3, jof(i0 + 2));
        if (i0 + 3 < 127) stage_be((i0 + 3) & 3, jof(i0 + 3));
        CP_COMMIT();
        if (i0 + 4 < 127) wrA = ldg_w(jof(i0 + 4));
        if (i0 + 5 < 127) wrB = ldg_w(jof(i0 + 5));

        // compute both j of the pair, no barrier between
        compute_j(i0);
        if (i0 + 1 < 127) compute_j(i0 + 1);
    }

    // ======================= fused CE head ==================================
    CP_WAIT0();
    __syncthreads();             // BE ring dead; reuse as W3 staging

    // W3[i] fp32 [e][n] -> smem bf16 [n][e] (rows 144B)
    {
        const float4* w3p =
            reinterpret_cast<const float4*>(w3g + (size_t)i * E_ * N_);
        __nv_bfloat16* W3S = reinterpret_cast<__nv_bfloat16*>(smem + OFF_W3S);
#pragma unroll
        for (int it = 0; it < 8; ++it) {
            int idx = it * 512 + tid;          // 4096 float4 total
            float4 f = w3p[idx];
            int e = idx >> 6, n0 = (idx & 63) * 4;
            W3S[(n0 + 0) * 72 + e] = __float2bfloat16(f.x);
            W3S[(n0 + 1) * 72 + e] = __float2bfloat16(f.y);
            W3S[(n0 + 2) * 72 + e] = __float2bfloat16(f.z);
            W3S[(n0 + 3) * 72 + e] = __float2bfloat16(f.w);
        }
    }

    // z + bias2 -> bf16 A-fragments
    uint32_t az[4][4];
#pragma unroll
    for (int kt = 0; kt < 4; ++kt) {
        float v[2][4];
#pragma unroll
        for (int p = 0; p < 2; ++p) {
            int nt = 2 * kt + p;
            float bx = sb2[nt * 8 + 2 * q], by = sb2[nt * 8 + 2 * q + 1];
            v[p][0] = zacc[nt][0] + bx; v[p][1] = zacc[nt][1] + by;
            v[p][2] = zacc[nt][2] + bx; v[p][3] = zacc[nt][3] + by;
        }
        __nv_bfloat162 p0 = __floats2bfloat162_rn(v[0][0], v[0][1]);
        __nv_bfloat162 p1 = __floats2bfloat162_rn(v[0][2], v[0][3]);
        __nv_bfloat162 p2 = __floats2bfloat162_rn(v[1][0], v[1][1]);
        __nv_bfloat162 p3 = __floats2bfloat162_rn(v[1][2], v[1][3]);
        az[kt][0] = *reinterpret_cast<uint32_t*>(&p0);
        az[kt][1] = *reinterpret_cast<uint32_t*>(&p1);
        az[kt][2] = *reinterpret_cast<uint32_t*>(&p2);
        az[kt][3] = *reinterpret_cast<uint32_t*>(&p3);
    }

    int xv[2];
    xv[0] = x[(size_t)(w * 16 + r4) * T_ + i];
    xv[1] = x[(size_t)(w * 16 + r4 + 8) * T_ + i];

    __syncthreads();             // W3S ready

    float sum[2] = {0.f, 0.f};
    float picked[2] = {0.f, 0.f};

#pragma unroll
    for (int n0 = 0; n0 < 4; ++n0) {           // 64 classes per chunk
        float c[8][4];
#pragma unroll
        for (int nt = 0; nt < 8; ++nt)
#pragma unroll
            for (int s = 0; s < 4; ++s) c[nt][s] = 0.f;
#pragma unroll
        for (int ntp = 0; ntp < 4; ++ntp) {
#pragma unroll
            for (int kt = 0; kt < 4; ++kt) {
                uint32_t b0, b1r, b2r, b3;
                LDSM_X4(b0, b1r, b2r, b3,
                        w3_off + (n0 * 64 + ntp * 16) * 144 + kt * 32);
                mma_bf16(c[2 * ntp + 0], az[kt], b0, b1r);
                mma_bf16(c[2 * ntp + 1], az[kt], b2r, b3);
            }
        }
#pragma unroll
        for (int nt = 0; nt < 8; ++nt)
#pragma unroll
            for (int s = 0; s < 4; ++s) {
                int n = n0 * 64 + nt * 8 + 2 * q + (s & 1);
                int hh = s >> 1;
                float v = c[nt][s];
                sum[hh] += __expf(v);
                if (n == xv[hh]) picked[hh] = v;
            }
    }

    // reduce over the 4 q-lanes (consecutive lanes r4*4+q)
#pragma unroll
    for (int hh = 0; hh < 2; ++hh) {
        float s = sum[hh], p = picked[hh];
        s += __shfl_xor_sync(0xffffffffu, s, 1);
        s += __shfl_xor_sync(0xffffffffu, s, 2);
        p += __shfl_xor_sync(0xffffffffu, p, 1);
        p += __shfl_xor_sync(0xffffffffu, p, 2);
        if (q == 0) {
            int row = w * 16 + r4 + 8 * hh;
            out[(size_t)row * T_ + i] = __logf(s) - p;
        }
    }
}

// ---------------------------------------------------------------------------
extern "C" void kernel_launch(void* const* d_in, const int* in_sizes, int n_in,
                              void* d_out, int out_size) {
    const int*   x    = (const int*)  d_in[0];  // [B,T]
    const float* emb  = (const float*)d_in[1];  // [N*T,E]
    const float* lin1 = (const float*)d_in[2];  // [T,T,E,H]
    const float* b1   = (const float*)d_in[3];  // [T,T,H]
    const float* lin2 = (const float*)d_in[4];  // [T,(T-1)*H,E]
    const float* b2   = (const float*)d_in[5];  // [T,E]
    const float* w3   = (const float*)d_in[6];  // [T,E,N]
    float* out = (float*)d_out;                 // [B,T]

    cudaFuncSetAttribute(fused_all_kernel,
                         cudaFuncAttributeMaxDynamicSharedMemorySize,
                         SMEM_TOTAL);

    gather_bf16_kernel<<<dim3(T_, B_ / 64), 128>>>(x, emb);
    fused_all_kernel<<<T_, 512, SMEM_TOTAL>>>(lin1, b1, lin2, b2, w3, x, out);
}

// round 13
// speedup vs baseline: 1.1494x; 1.0867x over previous
#include <cuda_runtime.h>
#include <cuda_bf16.h>
#include <cstdint>

// Problem constants
constexpr int B_ = 256;   // batch
constexpr int T_ = 128;   // trees
constexpr int N_ = 256;   // nodes (= classes)
constexpr int E_ = 64;    // embedding
constexpr int H_ = 16;    // hidden
constexpr int K2_ = (T_ - 1) * H_;  // 2032

// Scratch (device global; no runtime allocation)
__device__ __nv_bfloat16 g_be[T_ * B_ * E_];  // [j][b][e] bf16, 4 MB

// ---------------------------------------------------------------------------
// Kernel 1: gather embeddings (shifted index) -> bf16 [j][b][e]
// ---------------------------------------------------------------------------
__global__ void gather_bf16_kernel(const int* __restrict__ x,
                                   const float* __restrict__ emb) {
    int j    = blockIdx.x;
    int b    = blockIdx.y * 64 + (threadIdx.x >> 1);
    int half = threadIdx.x & 1;
    int row  = x[b * T_ + j] + j * N_;
    const float4* src =
        reinterpret_cast<const float4*>(emb + (size_t)row * E_ + half * 32);
    __nv_bfloat162 v[16];
#pragma unroll
    for (int k = 0; k < 8; ++k) {
        float4 f = src[k];
        v[2 * k + 0] = __floats2bfloat162_rn(f.x, f.y);
        v[2 * k + 1] = __floats2bfloat162_rn(f.z, f.w);
    }
    uint4* dst = reinterpret_cast<uint4*>(
        g_be + ((size_t)j * B_ + b) * E_ + half * 32);
    const uint4* vp = reinterpret_cast<const uint4*>(v);
#pragma unroll
    for (int k = 0; k < 4; ++k) dst[k] = vp[k];
}

// ---------------------------------------------------------------------------
// mma.sync m16n8k16 bf16 (fp32 accum) + ldmatrix helpers
// ---------------------------------------------------------------------------
__device__ __forceinline__ void mma_bf16(float* c, const uint32_t* a,
                                         uint32_t b0, uint32_t b1) {
    asm volatile(
        "mma.sync.aligned.m16n8k16.row.col.f32.bf16.bf16.f32 "
        "{%0,%1,%2,%3}, {%4,%5,%6,%7}, {%8,%9}, {%0,%1,%2,%3};"
        : "+f"(c[0]), "+f"(c[1]), "+f"(c[2]), "+f"(c[3])
        : "r"(a[0]), "r"(a[1]), "r"(a[2]), "r"(a[3]), "r"(b0), "r"(b1));
}

#define LDSM_X4(r0, r1, r2, r3, addr)                                     \
    asm volatile("ldmatrix.sync.aligned.m8n8.x4.shared.b16 "              \
                 "{%0,%1,%2,%3}, [%4];"                                   \
                 : "=r"(r0), "=r"(r1), "=r"(r2), "=r"(r3) : "r"(addr))

#define CP_ASYNC16(dst, src)                                         \
    asm volatile("cp.async.cg.shared.global [%0], [%1], 16;" ::      \
                 "r"(dst), "l"(src))
#define CP_COMMIT() asm volatile("cp.async.commit_group;" ::: "memory")
#define CP_WAIT1()  asm volatile("cp.async.wait_group 1;" ::: "memory")
#define CP_WAIT0()  asm volatile("cp.async.wait_group 0;" ::: "memory")

// Fused-kernel SMEM layout (bytes)
constexpr int BE_STRIDE = 144;              // 64 bf16 + 8 pad (conflict-free)
constexpr int BE_BUF    = 256 * BE_STRIDE;  // 36864 (256 batch rows)
constexpr int W1_STRIDE = 144;              // [h][e] bf16
constexpr int W1_BUF    = 16 * W1_STRIDE;   // 2304
constexpr int W2_STRIDE = 48;               // [e][h] bf16
constexpr int W2_BUF    = 64 * W2_STRIDE;   // 3072
constexpr int OFF_BE = 0;                            // 3 bufs = 110592
constexpr int OFF_W1 = OFF_BE + 3 * BE_BUF;          // 110592 (4 bufs)
constexpr int OFF_W2 = OFF_W1 + 4 * W1_BUF;          // 119808 (4 bufs)
constexpr int OFF_B1 = OFF_W2 + 4 * W2_BUF;          // 132096
constexpr int OFF_B2 = OFF_B1 + T_ * H_ * 4;         // 140288
constexpr int SMEM_TOTAL = OFF_B2 + E_ * 4;          // 140544
// W3 bf16 [n][e] staging overlays the dead BE ring in the epilogue
constexpr int OFF_W3S = 0;                  // 256 rows x 144B

// ---------------------------------------------------------------------------
// Kernel 2: fully fused stages 2..7. CTA = tree i, 512 threads = 16 warps,
// warp w owns batch rows [16w,16w+16). SOFTWARE-PIPELINED: each iteration
// runs GEMM1(jj+1) and GEMM2(jj) concurrently (independent chains).
// BE ring-3; W ring-4. All smem writes strictly post-barrier.
// ---------------------------------------------------------------------------
__global__ void __launch_bounds__(512, 1)
fused_all_kernel(const float* __restrict__ lin1,   // [T,T,E,H]
                 const float* __restrict__ b1,     // [T,T,H]
                 const float* __restrict__ lin2,   // [T,(T-1)*H,E]
                 const float* __restrict__ b2,     // [T,E]
                 const float* __restrict__ w3g,    // [T,E,N]
                 const int*   __restrict__ x,      // [B,T]
                 float* __restrict__ out) {        // [B,T]
    extern __shared__ char smem[];
    const int i    = blockIdx.x;
    const int tid  = threadIdx.x;
    const int w    = tid >> 5;
    const int lane = tid & 31;
    const int q    = lane & 3;
    const int r4   = lane >> 2;

    float* sb1 = reinterpret_cast<float*>(smem + OFF_B1);
    float* sb2 = reinterpret_cast<float*>(smem + OFF_B2);
    const uint32_t smem_u32 = (uint32_t)__cvta_generic_to_shared(smem);

    // ldmatrix lane-dependent base offsets (hoisted):
    const uint32_t a_off = smem_u32 + OFF_BE +
        (w * 16 + (lane & 15)) * BE_STRIDE + (lane >> 4) * 16;
    const int brow = (lane & 7) + ((lane >> 1) & 8);
    const int bcol = ((lane >> 3) & 1) * 16;
    const uint32_t w1_off = smem_u32 + OFF_W1 + brow * W1_STRIDE + bcol;
    const uint32_t w2_off = smem_u32 + OFF_W2 + brow * W2_STRIDE + bcol;
    const uint32_t w3_off = smem_u32 + OFF_W3S + brow * 144 + bcol;

    auto jof = [&](int jj) { return jj + (jj >= i); };

    auto stage_be = [&](int buf, int j) {
        uint32_t dst0 = smem_u32 + OFF_BE + buf * BE_BUF;
        const char* src =
            reinterpret_cast<const char*>(g_be + (size_t)j * B_ * E_);
#pragma unroll
        for (int u = 0; u < 4; ++u) {
            int c = tid + 512 * u;             // 2048 x 16B chunks
            int row = c >> 3, off = c & 7;
            CP_ASYNC16(dst0 + row * BE_STRIDE + off * 16, src + c * 16);
        }
    };

    struct WRegs { float2 v1, v2; };
    auto ldg_w = [&](int j) {
        WRegs r;
        r.v1 = reinterpret_cast<const float2*>(
            lin1 + (size_t)(i * T_ + j) * (E_ * H_))[tid];
        int kk = (j < i) ? j : j - 1;
        r.v2 = reinterpret_cast<const float2*>(
            lin2 + ((size_t)i * K2_ + (size_t)kk * H_) * E_)[tid];
        return r;
    };
    auto sts_w = [&](int buf, const WRegs& r) {
        __nv_bfloat16* w1 =
            reinterpret_cast<__nv_bfloat16*>(smem + OFF_W1 + buf * W1_BUF);
        {
            int idx = tid * 2;
            const float* f = reinterpret_cast<const float*>(&r.v1);
#pragma unroll
            for (int s = 0; s < 2; ++s) {
                int e = (idx + s) >> 4, hh = (idx + s) & 15;
                w1[hh * (W1_STRIDE / 2) + e] = __float2bfloat16(f[s]);
            }
        }
        __nv_bfloat16* w2 =
            reinterpret_cast<__nv_bfloat16*>(smem + OFF_W2 + buf * W2_BUF);
        {
            int idx = tid * 2;
            const float* f = reinterpret_cast<const float*>(&r.v2);
#pragma unroll
            for (int s = 0; s < 2; ++s) {
                int k = (idx + s) >> 6, e = (idx + s) & 63;
                w2[e * (W2_STRIDE / 2) + k] = __float2bfloat16(f[s]);
            }
        }
    };

    // ---- prologue ----------------------------------------------------------
#pragma unroll
    for (int u = 0; u < 4; ++u)
        sb1[tid + 512 * u] = b1[(size_t)i * T_ * H_ + tid + 512 * u];
    if (tid < E_) sb2[tid] = b2[(size_t)i * E_ + tid];

    stage_be(0, jof(0)); CP_COMMIT();
    stage_be(1, jof(1)); CP_COMMIT();
    {
        WRegs wa = ldg_w(jof(0)); sts_w(0, wa);
        WRegs wb = ldg_w(jof(1)); sts_w(1, wb);
    }
    WRegs wr = ldg_w(jof(2));          // invariant at loop top: wr = W(jj+2)

    CP_WAIT1();                        // BE(0) complete
    __syncthreads();                   // sts_w(0),(1) visible

    float zacc[8][4];
#pragma unroll
    for (int nt = 0; nt < 8; ++nt)
#pragma unroll
        for (int s = 0; s < 4; ++s) zacc[nt][s] = 0.f;

    // GEMM1(0) -> c1
    float c1[2][4];
    {
        const int j0 = jof(0);
#pragma unroll
        for (int nt = 0; nt < 2; ++nt) {
            float bv0 = sb1[j0 * H_ + nt * 8 + 2 * q];
            float bv1 = sb1[j0 * H_ + nt * 8 + 2 * q + 1];
            c1[nt][0] = bv0; c1[nt][1] = bv1;
            c1[nt][2] = bv0; c1[nt][3] = bv1;
        }
#pragma unroll
        for (int kt = 0; kt < 4; ++kt) {
            uint32_t a0, a1, a2r, a3;
            LDSM_X4(a0, a1, a2r, a3, a_off + kt * 32);
            uint32_t b0, b1r, b2r, b3;
            LDSM_X4(b0, b1r, b2r, b3, w1_off + kt * 32);
            uint32_t aa[4] = {a0, a1, a2r, a3};
            mma_bf16(c1[0], aa, b0, b1r);
            mma_bf16(c1[1], aa, b2r, b3);
        }
    }

    // ---- main loop: iter jj does relu/cvt(jj), GEMM1(jj+1) || GEMM2(jj) ----
    for (int jj = 0; jj < T_ - 1; ++jj) {
        // 1. relu + cvt c1 -> a2 (registers only)
#pragma unroll
        for (int nt = 0; nt < 2; ++nt)
#pragma unroll
            for (int s = 0; s < 4; ++s) c1[nt][s] = fmaxf(c1[nt][s], 0.f);
        uint32_t a2[4];
        {
            __nv_bfloat162 p0 = __floats2bfloat162_rn(c1[0][0], c1[0][1]);
            __nv_bfloat162 p1 = __floats2bfloat162_rn(c1[0][2], c1[0][3]);
            __nv_bfloat162 p2 = __floats2bfloat162_rn(c1[1][0], c1[1][1]);
            __nv_bfloat162 p3 = __floats2bfloat162_rn(c1[1][2], c1[1][3]);
            a2[0] = *reinterpret_cast<uint32_t*>(&p0);
            a2[1] = *reinterpret_cast<uint32_t*>(&p1);
            a2[2] = *reinterpret_cast<uint32_t*>(&p2);
            a2[3] = *reinterpret_cast<uint32_t*>(&p3);
        }

        // 2. wait BE(jj+1) + barrier (protects all smem writes below)
        CP_WAIT0();
        __syncthreads();

        // 3. post-barrier staging for jj+2
        if (jj + 2 < T_ - 1) {
            sts_w((jj + 2) & 3, wr);
            stage_be((jj + 2) % 3, jof(jj + 2));
        }
        CP_COMMIT();
        if (jj + 3 < T_ - 1) wr = ldg_w(jof(jj + 3));

        // 4. dual compute: GEMM1(jj+1) chain || GEMM2(jj) chain
        const uint32_t w2b = w2_off + (jj & 3) * W2_BUF;
        if (jj + 1 < T_ - 1) {
            const int jn = jof(jj + 1);
            const uint32_t beb = a_off + ((jj + 1) % 3) * BE_BUF;
            const uint32_t w1b = w1_off + ((jj + 1) & 3) * W1_BUF;
            float c1n[2][4];
#pragma unroll
            for (int nt = 0; nt < 2; ++nt) {
                float bv0 = sb1[jn * H_ + nt * 8 + 2 * q];
                float bv1 = sb1[jn * H_ + nt * 8 + 2 * q + 1];
                c1n[nt][0] = bv0; c1n[nt][1] = bv1;
                c1n[nt][2] = bv0; c1n[nt][3] = bv1;
            }
#pragma unroll
            for (int kt = 0; kt < 4; ++kt) {
                uint32_t a0, a1, a2r, a3;
                LDSM_X4(a0, a1, a2r, a3, beb + kt * 32);
                uint32_t b0, b1r, b2r, b3;
                LDSM_X4(b0, b1r, b2r, b3, w1b + kt * 32);
                uint32_t aa[4] = {a0, a1, a2r, a3};
                mma_bf16(c1n[0], aa, b0, b1r);
                mma_bf16(c1n[1], aa, b2r, b3);
                // interleaved GEMM2(jj) chunk kt (independent of c1n chain)
                uint32_t d0, d1, d2, d3;
                LDSM_X4(d0, d1, d2, d3, w2b + kt * 16 * W2_STRIDE);
                mma_bf16(zacc[2 * kt + 0], a2, d0, d1);
                mma_bf16(zacc[2 * kt + 1], a2, d2, d3);
            }
#pragma unroll
            for (int nt = 0; nt < 2; ++nt)
#pragma unroll
                for (int s = 0; s < 4; ++s) c1[nt][s] = c1n[nt][s];
        } else {
            // last iteration: only GEMM2(jj)
#pragma unroll
            for (int p = 0; p < 4; ++p) {
                uint32_t d0, d1, d2, d3;
                LDSM_X4(d0, d1, d2, d3, w2b + p * 16 * W2_STRIDE);
                mma_bf16(zacc[2 * p + 0], a2, d0, d1);
                mma_bf16(zacc[2 * p + 1], a2, d2, d3);
            }
        }
    }

    // ======================= fused CE head ==================================
    CP_WAIT0();
    __syncthreads();             // BE ring dead; reuse as W3 staging

    // W3[i] fp32 [e][n] -> smem bf16 [n][e] (rows 144B)
    {
        const float4* w3p =
            reinterpret_cast<const float4*>(w3g + (size_t)i * E_ * N_);
        __nv_bfloat16* W3S = reinterpret_cast<__nv_bfloat16*>(smem + OFF_W3S);
#pragma unroll
        for (int it = 0; it < 8; ++it) {
            int idx = it * 512 + tid;          // 4096 float4 total
            float4 f = w3p[idx];
            int e = idx >> 6, n0 = (idx & 63) * 4;
            W3S[(n0 + 0) * 72 + e] = __float2bfloat16(f.x);
            W3S[(n0 + 1) * 72 + e] = __float2bfloat16(f.y);
            W3S[(n0 + 2) * 72 + e] = __float2bfloat16(f.z);
            W3S[(n0 + 3) * 72 + e] = __float2bfloat16(f.w);
        }
    }

    // z + bias2 -> bf16 A-fragments
    uint32_t az[4][4];
#pragma unroll
    for (int kt = 0; kt < 4; ++kt) {
        float v[2][4];
#pragma unroll
        for (int p = 0; p < 2; ++p) {
            int nt = 2 * kt + p;
            float bx = sb2[nt * 8 + 2 * q], by = sb2[nt * 8 + 2 * q + 1];
            v[p][0] = zacc[nt][0] + bx; v[p][1] = zacc[nt][1] + by;
            v[p][2] = zacc[nt][2] + bx; v[p][3] = zacc[nt][3] + by;
        }
        __nv_bfloat162 p0 = __floats2bfloat162_rn(v[0][0], v[0][1]);
        __nv_bfloat162 p1 = __floats2bfloat162_rn(v[0][2], v[0][3]);
        __nv_bfloat162 p2 = __floats2bfloat162_rn(v[1][0], v[1][1]);
        __nv_bfloat162 p3 = __floats2bfloat162_rn(v[1][2], v[1][3]);
        az[kt][0] = *reinterpret_cast<uint32_t*>(&p0);
        az[kt][1] = *reinterpret_cast<uint32_t*>(&p1);
        az[kt][2] = *reinterpret_cast<uint32_t*>(&p2);
        az[kt][3] = *reinterpret_cast<uint32_t*>(&p3);
    }

    int xv[2];
    xv[0] = x[(size_t)(w * 16 + r4) * T_ + i];
    xv[1] = x[(size_t)(w * 16 + r4 + 8) * T_ + i];

    __syncthreads();             // W3S ready

    float sum[2] = {0.f, 0.f};
    float picked[2] = {0.f, 0.f};

#pragma unroll
    for (int n0 = 0; n0 < 4; ++n0) {           // 64 classes per chunk
        float c[8][4];
#pragma unroll
        for (int nt = 0; nt < 8; ++nt)
#pragma unroll
            for (int s = 0; s < 4; ++s) c[nt][s] = 0.f;
#pragma unroll
        for (int ntp = 0; ntp < 4; ++ntp) {
#pragma unroll
            for (int kt = 0; kt < 4; ++kt) {
                uint32_t b0, b1r, b2r, b3;
                LDSM_X4(b0, b1r, b2r, b3,
                        w3_off + (n0 * 64 + ntp * 16) * 144 + kt * 32);
                mma_bf16(c[2 * ntp + 0], az[kt], b0, b1r);
                mma_bf16(c[2 * ntp + 1], az[kt], b2r, b3);
            }
        }
#pragma unroll
        for (int nt = 0; nt < 8; ++nt)
#pragma unroll
            for (int s = 0; s < 4; ++s) {
                int n = n0 * 64 + nt * 8 + 2 * q + (s & 1);
                int hh = s >> 1;
                float v = c[nt][s];
                sum[hh] += __expf(v);
                if (n == xv[hh]) picked[hh] = v;
            }
    }

    // reduce over the 4 q-lanes (consecutive lanes r4*4+q)
#pragma unroll
    for (int hh = 0; hh < 2; ++hh) {
        float s = sum[hh], p = picked[hh];
        s += __shfl_xor_sync(0xffffffffu, s, 1);
        s += __shfl_xor_sync(0xffffffffu, s, 2);
        p += __shfl_xor_sync(0xffffffffu, p, 1);
        p += __shfl_xor_sync(0xffffffffu, p, 2);
        if (q == 0) {
            int row = w * 16 + r4 + 8 * hh;
            out[(size_t)row * T_ + i] = __logf(s) - p;
        }
    }
}

// ---------------------------------------------------------------------------
extern "C" void kernel_launch(void* const* d_in, const int* in_sizes, int n_in,
                              void* d_out, int out_size) {
    const int*   x    = (const int*)  d_in[0];  // [B,T]
    const float* emb  = (const float*)d_in[1];  // [N*T,E]
    const float* lin1 = (const float*)d_in[2];  // [T,T,E,H]
    const float* b1   = (const float*)d_in[3];  // [T,T,H]
    const float* lin2 = (const float*)d_in[4];  // [T,(T-1)*H,E]
    const float* b2   = (const float*)d_in[5];  // [T,E]
    const float* w3   = (const float*)d_in[6];  // [T,E,N]
    float* out = (float*)d_out;                 // [B,T]

    cudaFuncSetAttribute(fused_all_kernel,
                         cudaFuncAttributeMaxDynamicSharedMemorySize,
                         SMEM_TOTAL);

    gather_bf16_kernel<<<dim3(T_, B_ / 64), 128>>>(x, emb);
    fused_all_kernel<<<T_, 512, SMEM_TOTAL>>>(lin1, b1, lin2, b2, w3, x, out);
}

// round 14
// speedup vs baseline: 1.2012x; 1.0450x over previous
#include <cuda_runtime.h>
#include <cuda_bf16.h>
#include <cstdint>

// Problem constants
constexpr int B_ = 256;   // batch
constexpr int T_ = 128;   // trees
constexpr int N_ = 256;   // nodes (= classes)
constexpr int E_ = 64;    // embedding
constexpr int H_ = 16;    // hidden
constexpr int K2_ = (T_ - 1) * H_;  // 2032

// Fragment-ordered gathered embeddings:
// g_bef[ ((j*16 + strip)*4 + kt)*32 + lane ] = uint4 A-frag regs {a0,a1,a2,a3}
__device__ uint4 g_bef[T_ * 16 * 4 * 32];   // 4 MB

// ---------------------------------------------------------------------------
// mma.sync m16n8k16 bf16 (fp32 accum) + ldmatrix helpers
// ---------------------------------------------------------------------------
__device__ __forceinline__ void mma_bf16(float* c, const uint32_t* a,
                                         uint32_t b0, uint32_t b1) {
    asm volatile(
        "mma.sync.aligned.m16n8k16.row.col.f32.bf16.bf16.f32 "
        "{%0,%1,%2,%3}, {%4,%5,%6,%7}, {%8,%9}, {%0,%1,%2,%3};"
        : "+f"(c[0]), "+f"(c[1]), "+f"(c[2]), "+f"(c[3])
        : "r"(a[0]), "r"(a[1]), "r"(a[2]), "r"(a[3]), "r"(b0), "r"(b1));
}

#define LDSM_X4(r0, r1, r2, r3, addr)                                     \
    asm volatile("ldmatrix.sync.aligned.m8n8.x4.shared.b16 "              \
                 "{%0,%1,%2,%3}, [%4];"                                   \
                 : "=r"(r0), "=r"(r1), "=r"(r2), "=r"(r3) : "r"(addr))

// ---------------------------------------------------------------------------
// Kernel 1: gather embeddings (shifted index) AND emit A-fragments.
// grid = T (one CTA per tree-input j), 256 threads.
//   phase 1: thread b loads emb row for (b, j), cvt bf16, STS (144B rows)
//   phase 2: warps extract mma A-fragments via ldmatrix, STG.128 coalesced
// ---------------------------------------------------------------------------
__global__ void __launch_bounds__(256)
gather_frag_kernel(const int* __restrict__ x,
                   const float* __restrict__ emb) {
    __shared__ __align__(16) char sm[256 * 144];
    const int j    = blockIdx.x;
    const int tid  = threadIdx.x;
    const int w    = tid >> 5;
    const int lane = tid & 31;
    const uint32_t smem_u32 = (uint32_t)__cvta_generic_to_shared(sm);

    // phase 1: one emb row per thread
    {
        const int row = x[tid * T_ + j] + j * N_;
        const float4* src =
            reinterpret_cast<const float4*>(emb + (size_t)row * E_);
        char* dst = sm + tid * 144;
#pragma unroll
        for (int k = 0; k < 8; ++k) {
            float4 f0 = src[2 * k], f1 = src[2 * k + 1];
            __nv_bfloat162 p0 = __floats2bfloat162_rn(f0.x, f0.y);
            __nv_bfloat162 p1 = __floats2bfloat162_rn(f0.z, f0.w);
            __nv_bfloat162 p2 = __floats2bfloat162_rn(f1.x, f1.y);
            __nv_bfloat162 p3 = __floats2bfloat162_rn(f1.z, f1.w);
            uint4 v;
            v.x = *reinterpret_cast<uint32_t*>(&p0);
            v.y = *reinterpret_cast<uint32_t*>(&p1);
            v.z = *reinterpret_cast<uint32_t*>(&p2);
            v.w = *reinterpret_cast<uint32_t*>(&p3);
            *reinterpret_cast<uint4*>(dst + k * 16) = v;
        }
    }
    __syncthreads();

    // phase 2: fragment extraction (identical addressing to the old mainloop)
#pragma unroll
    for (int sg = 0; sg < 2; ++sg) {
        const int s = w + 8 * sg;
        const uint32_t a_off = smem_u32 +
            (s * 16 + (lane & 15)) * 144 + (lane >> 4) * 16;
#pragma unroll
        for (int kt = 0; kt < 4; ++kt) {
            uint32_t r0, r1, r2, r3;
            LDSM_X4(r0, r1, r2, r3, a_off + kt * 32);
            uint4 v; v.x = r0; v.y = r1; v.z = r2; v.w = r3;
            g_bef[((size_t)(j * 16 + s) * 4 + kt) * 32 + lane] = v;
        }
    }
}

// ---------------------------------------------------------------------------
// Fused-kernel SMEM layout (bytes)
// ---------------------------------------------------------------------------
constexpr int W1_STRIDE = 144;              // [h][e] bf16
constexpr int W1_BUF    = 16 * W1_STRIDE;   // 2304
constexpr int W2_STRIDE = 48;               // [e][h] bf16
constexpr int W2_BUF    = 64 * W2_STRIDE;   // 3072
constexpr int OFF_W1 = 0;                            // 2 bufs
constexpr int OFF_W2 = OFF_W1 + 2 * W1_BUF;          // 4608 (2 bufs)
constexpr int OFF_B1 = OFF_W2 + 2 * W2_BUF;          // 10752
constexpr int OFF_W3S = 0;                  // head: 256 rows x 144B (overlay)
constexpr int OFF_B2 = 36864;               // after W3S region
constexpr int SMEM_TOTAL = OFF_B2 + E_ * 4; // 37120

// ---------------------------------------------------------------------------
// Kernel 2: fully fused stages 2..7. CTA = tree i, 512 threads = 16 warps,
// warp w owns batch rows [16w,16w+16). A-operand: DIRECT LDG.128 of
// pre-swizzled fragments (register prefetch depth 1) — zero smem, zero
// cp.async for BE. W1/W2: smem ring-2 (one barrier per iteration, guards
// only the 4KB weight stage).
// ---------------------------------------------------------------------------
__global__ void __launch_bounds__(512, 1)
fused_all_kernel(const float* __restrict__ lin1,   // [T,T,E,H]
                 const float* __restrict__ b1,     // [T,T,H]
                 const float* __restrict__ lin2,   // [T,(T-1)*H,E]
                 const float* __restrict__ b2,     // [T,E]
                 const float* __restrict__ w3g,    // [T,E,N]
                 const int*   __restrict__ x,      // [B,T]
                 float* __restrict__ out) {        // [B,T]
    extern __shared__ char smem[];
    const int i    = blockIdx.x;
    const int tid  = threadIdx.x;
    const int w    = tid >> 5;
    const int lane = tid & 31;
    const int q    = lane & 3;
    const int r4   = lane >> 2;

    float* sb1 = reinterpret_cast<float*>(smem + OFF_B1);
    float* sb2 = reinterpret_cast<float*>(smem + OFF_B2);
    const uint32_t smem_u32 = (uint32_t)__cvta_generic_to_shared(smem);

    // ldmatrix lane-dependent base offsets for B-operands (hoisted):
    const int brow = (lane & 7) + ((lane >> 1) & 8);
    const int bcol = ((lane >> 3) & 1) * 16;
    const uint32_t w1_off = smem_u32 + OFF_W1 + brow * W1_STRIDE + bcol;
    const uint32_t w2_off = smem_u32 + OFF_W2 + brow * W2_STRIDE + bcol;
    const uint32_t w3_off = smem_u32 + OFF_W3S + brow * 144 + bcol;

    auto jof = [&](int jj) { return jj + (jj >= i); };

    // A-fragment direct load: 4 coalesced uint4 per warp per j
    auto ldg_a = [&](int j, uint4* a) {
        const uint4* p = g_bef + (size_t)(j * 16 + w) * 4 * 32 + lane;
#pragma unroll
        for (int kt = 0; kt < 4; ++kt) a[kt] = p[kt * 32];
    };

    struct WRegs { float2 v1, v2; };
    auto ldg_w = [&](int j) {
        WRegs r;
        r.v1 = reinterpret_cast<const float2*>(
            lin1 + (size_t)(i * T_ + j) * (E_ * H_))[tid];
        int kk = (j < i) ? j : j - 1;
        r.v2 = reinterpret_cast<const float2*>(
            lin2 + ((size_t)i * K2_ + (size_t)kk * H_) * E_)[tid];
        return r;
    };
    auto sts_w = [&](int buf, const WRegs& r) {
        __nv_bfloat16* w1 =
            reinterpret_cast<__nv_bfloat16*>(smem + OFF_W1 + buf * W1_BUF);
        {
            int idx = tid * 2;
            const float* f = reinterpret_cast<const float*>(&r.v1);
#pragma unroll
            for (int s = 0; s < 2; ++s) {
                int e = (idx + s) >> 4, hh = (idx + s) & 15;
                w1[hh * (W1_STRIDE / 2) + e] = __float2bfloat16(f[s]);
            }
        }
        __nv_bfloat16* w2 =
            reinterpret_cast<__nv_bfloat16*>(smem + OFF_W2 + buf * W2_BUF);
        {
            int idx = tid * 2;
            const float* f = reinterpret_cast<const float*>(&r.v2);
#pragma unroll
            for (int s = 0; s < 2; ++s) {
                int k = (idx + s) >> 6, e = (idx + s) & 63;
                w2[e * (W2_STRIDE / 2) + k] = __float2bfloat16(f[s]);
            }
        }
    };

    // ---- prologue ----------------------------------------------------------
#pragma unroll
    for (int u = 0; u < 4; ++u)
        sb1[tid + 512 * u] = b1[(size_t)i * T_ * H_ + tid + 512 * u];
    if (tid < E_) sb2[tid] = b2[(size_t)i * E_ + tid];

    {
        WRegs wa = ldg_w(jof(0));
        sts_w(0, wa);
    }
    WRegs wr = ldg_w(jof(1));          // invariant at loop top: wr = W(jj+1)

    uint4 a_cur[4], a_nxt[4];
    ldg_a(jof(0), a_cur);

    float zacc[8][4];
#pragma unroll
    for (int nt = 0; nt < 8; ++nt)
#pragma unroll
        for (int s = 0; s < 4; ++s) zacc[nt][s] = 0.f;

    // ---- main loop over jj (j != i) ---------------------------------------
    for (int jj = 0; jj < T_ - 1; ++jj) {
        const int j = jof(jj);

        __syncthreads();         // W(jj) visible; W buf (jj+1)&1 free

        // prefetch A(jj+1) (independent of everything below)
        if (jj + 1 < T_ - 1) ldg_a(jof(jj + 1), a_nxt);
        // stage W(jj+1); refill W regs for jj+2
        if (jj + 1 < T_ - 1) sts_w((jj + 1) & 1, wr);
        if (jj + 2 < T_ - 1) wr = ldg_w(jof(jj + 2));

        const uint32_t w1b = w1_off + (jj & 1) * W1_BUF;
        const uint32_t w2b = w2_off + (jj & 1) * W2_BUF;

        // GEMM1: tmp[16,16] = BE[16,64] @ W1[64,16] (+bias1)
        float c1[2][4];
#pragma unroll
        for (int nt = 0; nt < 2; ++nt) {
            float bv0 = sb1[j * H_ + nt * 8 + 2 * q];
            float bv1 = sb1[j * H_ + nt * 8 + 2 * q + 1];
            c1[nt][0] = bv0; c1[nt][1] = bv1;
            c1[nt][2] = bv0; c1[nt][3] = bv1;
        }
#pragma unroll
        for (int kt = 0; kt < 4; ++kt) {
            uint32_t b0, b1r, b2r, b3;
            LDSM_X4(b0, b1r, b2r, b3, w1b + kt * 32);
            const uint32_t* aa = reinterpret_cast<const uint32_t*>(&a_cur[kt]);
            mma_bf16(c1[0], aa, b0, b1r);
            mma_bf16(c1[1], aa, b2r, b3);
        }

        // relu + cvt C-frags -> GEMM2 A-frag (registers only)
#pragma unroll
        for (int nt = 0; nt < 2; ++nt)
#pragma unroll
            for (int s = 0; s < 4; ++s) c1[nt][s] = fmaxf(c1[nt][s], 0.f);
        uint32_t a2[4];
        {
            __nv_bfloat162 p0 = __floats2bfloat162_rn(c1[0][0], c1[0][1]);
            __nv_bfloat162 p1 = __floats2bfloat162_rn(c1[0][2], c1[0][3]);
            __nv_bfloat162 p2 = __floats2bfloat162_rn(c1[1][0], c1[1][1]);
            __nv_bfloat162 p3 = __floats2bfloat162_rn(c1[1][2], c1[1][3]);
            a2[0] = *reinterpret_cast<uint32_t*>(&p0);
            a2[1] = *reinterpret_cast<uint32_t*>(&p1);
            a2[2] = *reinterpret_cast<uint32_t*>(&p2);
            a2[3] = *reinterpret_cast<uint32_t*>(&p3);
        }

        // GEMM2: z[16,64] += tmp[16,16] @ W2[16,64]
#pragma unroll
        for (int p = 0; p < 4; ++p) {
            uint32_t b0, b1r, b2r, b3;
            LDSM_X4(b0, b1r, b2r, b3, w2b + p * 16 * W2_STRIDE);
            mma_bf16(zacc[2 * p + 0], a2, b0, b1r);
            mma_bf16(zacc[2 * p + 1], a2, b2r, b3);
        }

#pragma unroll
        for (int kt = 0; kt < 4; ++kt) a_cur[kt] = a_nxt[kt];
    }

    // ======================= fused CE head ==================================
    __syncthreads();             // mainloop smem dead; reuse as W3 staging

    // W3[i] fp32 [e][n] -> smem bf16 [n][e] (rows 144B)
    {
        const float4* w3p =
            reinterpret_cast<const float4*>(w3g + (size_t)i * E_ * N_);
        __nv_bfloat16* W3S = reinterpret_cast<__nv_bfloat16*>(smem + OFF_W3S);
#pragma unroll
        for (int it = 0; it < 8; ++it) {
            int idx = it * 512 + tid;          // 4096 float4 total
            float4 f = w3p[idx];
            int e = idx >> 6, n0 = (idx & 63) * 4;
            W3S[(n0 + 0) * 72 + e] = __float2bfloat16(f.x);
            W3S[(n0 + 1) * 72 + e] = __float2bfloat16(f.y);
            W3S[(n0 + 2) * 72 + e] = __float2bfloat16(f.z);
            W3S[(n0 + 3) * 72 + e] = __float2bfloat16(f.w);
        }
    }

    // z + bias2 -> bf16 A-fragments
    uint32_t az[4][4];
#pragma unroll
    for (int kt = 0; kt < 4; ++kt) {
        float v[2][4];
#pragma unroll
        for (int p = 0; p < 2; ++p) {
            int nt = 2 * kt + p;
            float bx = sb2[nt * 8 + 2 * q], by = sb2[nt * 8 + 2 * q + 1];
            v[p][0] = zacc[nt][0] + bx; v[p][1] = zacc[nt][1] + by;
            v[p][2] = zacc[nt][2] + bx; v[p][3] = zacc[nt][3] + by;
        }
        __nv_bfloat162 p0 = __floats2bfloat162_rn(v[0][0], v[0][1]);
        __nv_bfloat162 p1 = __floats2bfloat162_rn(v[0][2], v[0][3]);
        __nv_bfloat162 p2 = __floats2bfloat162_rn(v[1][0], v[1][1]);
        __nv_bfloat162 p3 = __floats2bfloat162_rn(v[1][2], v[1][3]);
        az[kt][0] = *reinterpret_cast<uint32_t*>(&p0);
        az[kt][1] = *reinterpret_cast<uint32_t*>(&p1);
        az[kt][2] = *reinterpret_cast<uint32_t*>(&p2);
        az[kt][3] = *reinterpret_cast<uint32_t*>(&p3);
    }

    int xv[2];
    xv[0] = x[(size_t)(w * 16 + r4) * T_ + i];
    xv[1] = x[(size_t)(w * 16 + r4 + 8) * T_ + i];

    __syncthreads();             // W3S ready

    float sum[2] = {0.f, 0.f};
    float picked[2] = {0.f, 0.f};

#pragma unroll
    for (int n0 = 0; n0 < 4; ++n0) {           // 64 classes per chunk
        float c[8][4];
#pragma unroll
        for (int nt = 0; nt < 8; ++nt)
#pragma unroll
            for (int s = 0; s < 4; ++s) c[nt][s] = 0.f;
#pragma unroll
        for (int ntp = 0; ntp < 4; ++ntp) {
#pragma unroll
            for (int kt = 0; kt < 4; ++kt) {
                uint32_t b0, b1r, b2r, b3;
                LDSM_X4(b0, b1r, b2r, b3,
                        w3_off + (n0 * 64 + ntp * 16) * 144 + kt * 32);
                mma_bf16(c[2 * ntp + 0], az[kt], b0, b1r);
                mma_bf16(c[2 * ntp + 1], az[kt], b2r, b3);
            }
        }
#pragma unroll
        for (int nt = 0; nt < 8; ++nt)
#pragma unroll
            for (int s = 0; s < 4; ++s) {
                int n = n0 * 64 + nt * 8 + 2 * q + (s & 1);
                int hh = s >> 1;
                float v = c[nt][s];
                sum[hh] += __expf(v);
                if (n == xv[hh]) picked[hh] = v;
            }
    }

    // reduce over the 4 q-lanes (consecutive lanes r4*4+q)
#pragma unroll
    for (int hh = 0; hh < 2; ++hh) {
        float s = sum[hh], p = picked[hh];
        s += __shfl_xor_sync(0xffffffffu, s, 1);
        s += __shfl_xor_sync(0xffffffffu, s, 2);
        p += __shfl_xor_sync(0xffffffffu, p, 1);
        p += __shfl_xor_sync(0xffffffffu, p, 2);
        if (q == 0) {
            int row = w * 16 + r4 + 8 * hh;
            out[(size_t)row * T_ + i] = __logf(s) - p;
        }
    }
}

// ---------------------------------------------------------------------------
extern "C" void kernel_launch(void* const* d_in, const int* in_sizes, int n_in,
                              void* d_out, int out_size) {
    const int*   x    = (const int*)  d_in[0];  // [B,T]
    const float* emb  = (const float*)d_in[1];  // [N*T,E]
    const float* lin1 = (const float*)d_in[2];  // [T,T,E,H]
    const float* b1   = (const float*)d_in[3];  // [T,T,H]
    const float* lin2 = (const float*)d_in[4];  // [T,(T-1)*H,E]
    const float* b2   = (const float*)d_in[5];  // [T,E]
    const float* w3   = (const float*)d_in[6];  // [T,E,N]
    float* out = (float*)d_out;                 // [B,T]

    cudaFuncSetAttribute(fused_all_kernel,
                         cudaFuncAttributeMaxDynamicSharedMemorySize,
                         SMEM_TOTAL);

    gather_frag_kernel<<<T_, 256>>>(x, emb);
    fused_all_kernel<<<T_, 512, SMEM_TOTAL>>>(lin1, b1, lin2, b2, w3, x, out);
}

// round 15
// speedup vs baseline: 1.2554x; 1.0451x over previous
#include <cuda_runtime.h>
#include <cuda_bf16.h>
#include <cstdint>

// Problem constants
constexpr int B_ = 256;   // batch
constexpr int T_ = 128;   // trees
constexpr int N_ = 256;   // nodes (= classes)
constexpr int E_ = 64;    // embedding
constexpr int H_ = 16;    // hidden
constexpr int K2_ = (T_ - 1) * H_;  // 2032

// Fragment-ordered gathered embeddings:
// g_bef[ ((j*16 + strip)*4 + kt)*32 + lane ] = uint4 A-frag regs {a0,a1,a2,a3}
__device__ uint4 g_bef[T_ * 16 * 4 * 32];   // 4 MB

// ---------------------------------------------------------------------------
// mma.sync m16n8k16 bf16 (fp32 accum) + ldmatrix + mbarrier helpers
// ---------------------------------------------------------------------------
__device__ __forceinline__ void mma_bf16(float* c, const uint32_t* a,
                                         uint32_t b0, uint32_t b1) {
    asm volatile(
        "mma.sync.aligned.m16n8k16.row.col.f32.bf16.bf16.f32 "
        "{%0,%1,%2,%3}, {%4,%5,%6,%7}, {%8,%9}, {%0,%1,%2,%3};"
        : "+f"(c[0]), "+f"(c[1]), "+f"(c[2]), "+f"(c[3])
        : "r"(a[0]), "r"(a[1]), "r"(a[2]), "r"(a[3]), "r"(b0), "r"(b1));
}

#define LDSM_X4(r0, r1, r2, r3, addr)                                     \
    asm volatile("ldmatrix.sync.aligned.m8n8.x4.shared.b16 "              \
                 "{%0,%1,%2,%3}, [%4];"                                   \
                 : "=r"(r0), "=r"(r1), "=r"(r2), "=r"(r3) : "r"(addr))

#define MBAR_INIT(a, c) \
    asm volatile("mbarrier.init.shared.b64 [%0], %1;" :: "r"(a), "r"(c) : "memory")
#define MBAR_ARRIVE(a) \
    asm volatile("mbarrier.arrive.shared.b64 _, [%0];" :: "r"(a) : "memory")
#define MBAR_WAIT(a, par) do {                                              \
    uint32_t _m = (a), _p = (par), _d;                                      \
    asm volatile("{\n\t.reg .pred p;\n\t"                                   \
        "mbarrier.try_wait.parity.acquire.cta.shared::cta.b64 p, [%1], %2;\n\t" \
        "selp.b32 %0, 1, 0, p;\n\t}" : "=r"(_d) : "r"(_m), "r"(_p) : "memory"); \
    if (!_d) {                                                              \
        asm volatile("{\n\t.reg .pred P1;\n\tWL_%=:\n\t"                    \
            "mbarrier.try_wait.parity.acquire.cta.shared::cta.b64 P1, [%0], %1, 0x989680;\n\t" \
            "@P1 bra.uni WD_%=;\n\tbra.uni WL_%=;\n\tWD_%=:\n\t}"           \
            :: "r"(_m), "r"(_p) : "memory");                                \
    }                                                                       \
} while (0)

// ---------------------------------------------------------------------------
// Kernel 1: gather embeddings (shifted index) AND emit A-fragments.
// ---------------------------------------------------------------------------
__global__ void __launch_bounds__(256)
gather_frag_kernel(const int* __restrict__ x,
                   const float* __restrict__ emb) {
    __shared__ __align__(16) char sm[256 * 144];
    const int j    = blockIdx.x;
    const int tid  = threadIdx.x;
    const int w    = tid >> 5;
    const int lane = tid & 31;
    const uint32_t smem_u32 = (uint32_t)__cvta_generic_to_shared(sm);

    {
        const int row = x[tid * T_ + j] + j * N_;
        const float4* src =
            reinterpret_cast<const float4*>(emb + (size_t)row * E_);
        char* dst = sm + tid * 144;
#pragma unroll
        for (int k = 0; k < 8; ++k) {
            float4 f0 = src[2 * k], f1 = src[2 * k + 1];
            __nv_bfloat162 p0 = __floats2bfloat162_rn(f0.x, f0.y);
            __nv_bfloat162 p1 = __floats2bfloat162_rn(f0.z, f0.w);
            __nv_bfloat162 p2 = __floats2bfloat162_rn(f1.x, f1.y);
            __nv_bfloat162 p3 = __floats2bfloat162_rn(f1.z, f1.w);
            uint4 v;
            v.x = *reinterpret_cast<uint32_t*>(&p0);
            v.y = *reinterpret_cast<uint32_t*>(&p1);
            v.z = *reinterpret_cast<uint32_t*>(&p2);
            v.w = *reinterpret_cast<uint32_t*>(&p3);
            *reinterpret_cast<uint4*>(dst + k * 16) = v;
        }
    }
    __syncthreads();

#pragma unroll
    for (int sg = 0; sg < 2; ++sg) {
        const int s = w + 8 * sg;
        const uint32_t a_off = smem_u32 +
            (s * 16 + (lane & 15)) * 144 + (lane >> 4) * 16;
#pragma unroll
        for (int kt = 0; kt < 4; ++kt) {
            uint32_t r0, r1, r2, r3;
            LDSM_X4(r0, r1, r2, r3, a_off + kt * 32);
            uint4 v; v.x = r0; v.y = r1; v.z = r2; v.w = r3;
            g_bef[((size_t)(j * 16 + s) * 4 + kt) * 32 + lane] = v;
        }
    }
}

// ---------------------------------------------------------------------------
// Fused-kernel SMEM layout (bytes)
// ---------------------------------------------------------------------------
constexpr int W1_STRIDE = 144;              // [h][e] bf16
constexpr int W1_BUF    = 16 * W1_STRIDE;   // 2304
constexpr int W2_STRIDE = 48;               // [e][h] bf16
constexpr int W2_BUF    = 64 * W2_STRIDE;   // 3072
constexpr int NSTAGE    = 4;
constexpr int OFF_MBAR  = 0;                          // 8 mbarriers (64B)
constexpr int OFF_W1    = 64;                         // 4 bufs
constexpr int OFF_W2    = OFF_W1 + NSTAGE * W1_BUF;   // 9280
constexpr int OFF_B1    = OFF_W2 + NSTAGE * W2_BUF;   // 21568
constexpr int OFF_B2    = OFF_B1 + T_ * H_ * 4;       // 29760
constexpr int OFF_W3S   = 30016;                      // 256 rows x 144B
constexpr int SMEM_TOTAL = OFF_W3S + 256 * 144;       // 66880

constexpr int NTHREADS  = 576;   // 16 consumer warps + 2 producer warps

// ---------------------------------------------------------------------------
// Kernel 2: warp-specialized fused stages 2..7. CTA = tree i.
// Consumers (warps 0-15): m16 strip each, A via direct LDG of g_bef,
//   W via LDSM from a 4-deep mbarrier ring. NO __syncthreads in mainloop.
// Producers (warps 16-17): LDG fp32 weights -> cvt bf16 -> STS ring.
// ---------------------------------------------------------------------------
__global__ void __launch_bounds__(NTHREADS, 1)
fused_all_kernel(const float* __restrict__ lin1,   // [T,T,E,H]
                 const float* __restrict__ b1,     // [T,T,H]
                 const float* __restrict__ lin2,   // [T,(T-1)*H,E]
                 const float* __restrict__ b2,     // [T,E]
                 const float* __restrict__ w3g,    // [T,E,N]
                 const int*   __restrict__ x,      // [B,T]
                 float* __restrict__ out) {        // [B,T]
    extern __shared__ char smem[];
    const int i    = blockIdx.x;
    const int tid  = threadIdx.x;
    const int w    = tid >> 5;
    const int lane = tid & 31;
    const int q    = lane & 3;
    const int r4   = lane >> 2;

    float* sb1 = reinterpret_cast<float*>(smem + OFF_B1);
    float* sb2 = reinterpret_cast<float*>(smem + OFF_B2);
    const uint32_t smem_u32 = (uint32_t)__cvta_generic_to_shared(smem);
    const uint32_t mb_full  = smem_u32 + OFF_MBAR;        // full[s]  = +8s
    const uint32_t mb_empty = smem_u32 + OFF_MBAR + 32;   // empty[s] = +8s

    auto jof = [&](int jj) { return jj + (jj >= i); };

    // ---- init: mbarriers + biases, one barrier before pipeline start -------
    if (tid == 0) {
#pragma unroll
        for (int s = 0; s < NSTAGE; ++s) {
            MBAR_INIT(mb_full + 8 * s, 64);    // 64 producer threads arrive
            MBAR_INIT(mb_empty + 8 * s, 512);  // 512 consumer threads arrive
        }
    }
    if (tid < 512) {
#pragma unroll
        for (int u = 0; u < 4; ++u)
            sb1[tid + 512 * u] = b1[(size_t)i * T_ * H_ + tid + 512 * u];
        if (tid < E_) sb2[tid] = b2[(size_t)i * E_ + tid];
    }
    __syncthreads();

    if (w >= 16) {
        // =================== PRODUCER (warps 16,17) =========================
        const int ptid = tid - 512;            // 0..63
        for (int jj = 0; jj < T_ - 1; ++jj) {
            const int s = jj & 3;
            const int j = jof(jj);
            MBAR_WAIT(mb_empty + 8 * s, ((jj >> 2) & 1) ^ 1);

            // W1[i,j]: thread ptid owns e=ptid (16 floats h=0..15)
            {
                const float4* p = reinterpret_cast<const float4*>(
                    lin1 + (size_t)(i * T_ + j) * (E_ * H_) + ptid * 16);
                __nv_bfloat16* w1 = reinterpret_cast<__nv_bfloat16*>(
                    smem + OFF_W1 + s * W1_BUF);
#pragma unroll
                for (int v4 = 0; v4 < 4; ++v4) {
                    float4 f = p[v4];
                    const float* fv = reinterpret_cast<const float*>(&f);
#pragma unroll
                    for (int u = 0; u < 4; ++u) {
                        int h = v4 * 4 + u;
                        w1[h * (W1_STRIDE / 2) + ptid] = __float2bfloat16(fv[u]);
                    }
                }
            }
            // W2 rows: thread ptid owns idx = ptid*16 + 0..15
            {
                const int kk = (j < i) ? j : j - 1;
                const float4* p = reinterpret_cast<const float4*>(
                    lin2 + ((size_t)i * K2_ + (size_t)kk * H_) * E_ + ptid * 16);
                __nv_bfloat16* w2 = reinterpret_cast<__nv_bfloat16*>(
                    smem + OFF_W2 + s * W2_BUF);
#pragma unroll
                for (int v4 = 0; v4 < 4; ++v4) {
                    float4 f = p[v4];
                    const float* fv = reinterpret_cast<const float*>(&f);
#pragma unroll
                    for (int u = 0; u < 4; ++u) {
                        int idx = ptid * 16 + v4 * 4 + u;
                        int k = idx >> 6, e = idx & 63;
                        w2[e * (W2_STRIDE / 2) + k] = __float2bfloat16(fv[u]);
                    }
                }
            }
            MBAR_ARRIVE(mb_full + 8 * s);      // release: STS visible
        }
    } else {
        // =================== CONSUMER (warps 0-15) ==========================
        const int brow = (lane & 7) + ((lane >> 1) & 8);
        const int bcol = ((lane >> 3) & 1) * 16;
        const uint32_t w1_off = smem_u32 + OFF_W1 + brow * W1_STRIDE + bcol;
        const uint32_t w2_off = smem_u32 + OFF_W2 + brow * W2_STRIDE + bcol;

        auto ldg_a = [&](int j, uint4* a) {
            const uint4* p = g_bef + (size_t)(j * 16 + w) * 4 * 32 + lane;
#pragma unroll
            for (int kt = 0; kt < 4; ++kt) a[kt] = p[kt * 32];
        };

        uint4 a_cur[4], a_nxt[4];
        ldg_a(jof(0), a_cur);

        float zacc[8][4];
#pragma unroll
        for (int nt = 0; nt < 8; ++nt)
#pragma unroll
            for (int s = 0; s < 4; ++s) zacc[nt][s] = 0.f;

        for (int jj = 0; jj < T_ - 1; ++jj) {
            const int s = jj & 3;
            const int j = jof(jj);

            if (jj + 1 < T_ - 1) ldg_a(jof(jj + 1), a_nxt);

            MBAR_WAIT(mb_full + 8 * s, (jj >> 2) & 1);   // acquire

            const uint32_t w1b = w1_off + s * W1_BUF;
            const uint32_t w2b = w2_off + s * W2_BUF;

            // GEMM1: tmp[16,16] = BE[16,64] @ W1[64,16] (+bias1)
            float c1[2][4];
#pragma unroll
            for (int nt = 0; nt < 2; ++nt) {
                float bv0 = sb1[j * H_ + nt * 8 + 2 * q];
                float bv1 = sb1[j * H_ + nt * 8 + 2 * q + 1];
                c1[nt][0] = bv0; c1[nt][1] = bv1;
                c1[nt][2] = bv0; c1[nt][3] = bv1;
            }
#pragma unroll
            for (int kt = 0; kt < 4; ++kt) {
                uint32_t b0, b1r, b2r, b3;
                LDSM_X4(b0, b1r, b2r, b3, w1b + kt * 32);
                const uint32_t* aa =
                    reinterpret_cast<const uint32_t*>(&a_cur[kt]);
                mma_bf16(c1[0], aa, b0, b1r);
                mma_bf16(c1[1], aa, b2r, b3);
            }

            // W2 fragments (last smem reads of stage s)
            uint32_t d[4][4];
#pragma unroll
            for (int p = 0; p < 4; ++p)
                LDSM_X4(d[p][0], d[p][1], d[p][2], d[p][3],
                        w2b + p * 16 * W2_STRIDE);

            MBAR_ARRIVE(mb_empty + 8 * s);     // stage s free for producer

            // relu + cvt -> GEMM2 A-frag
#pragma unroll
            for (int nt = 0; nt < 2; ++nt)
#pragma unroll
                for (int u = 0; u < 4; ++u) c1[nt][u] = fmaxf(c1[nt][u], 0.f);
            uint32_t a2[4];
            {
                __nv_bfloat162 p0 = __floats2bfloat162_rn(c1[0][0], c1[0][1]);
                __nv_bfloat162 p1 = __floats2bfloat162_rn(c1[0][2], c1[0][3]);
                __nv_bfloat162 p2 = __floats2bfloat162_rn(c1[1][0], c1[1][1]);
                __nv_bfloat162 p3 = __floats2bfloat162_rn(c1[1][2], c1[1][3]);
                a2[0] = *reinterpret_cast<uint32_t*>(&p0);
                a2[1] = *reinterpret_cast<uint32_t*>(&p1);
                a2[2] = *reinterpret_cast<uint32_t*>(&p2);
                a2[3] = *reinterpret_cast<uint32_t*>(&p3);
            }

            // GEMM2: z[16,64] += tmp[16,16] @ W2[16,64]
#pragma unroll
            for (int p = 0; p < 4; ++p) {
                mma_bf16(zacc[2 * p + 0], a2, d[p][0], d[p][1]);
                mma_bf16(zacc[2 * p + 1], a2, d[p][2], d[p][3]);
            }

#pragma unroll
            for (int kt = 0; kt < 4; ++kt) a_cur[kt] = a_nxt[kt];
        }

        // stash zacc in registers; fall through to head
        // (head code below uses zacc directly)
        __syncthreads();         // join with producers; smem ring dead

        // ---- fused CE head -------------------------------------------------
        // W3[i] fp32 [e][n] -> smem bf16 [n][e] (rows 144B)
        {
            const float4* w3p =
                reinterpret_cast<const float4*>(w3g + (size_t)i * E_ * N_);
            __nv_bfloat16* W3S =
                reinterpret_cast<__nv_bfloat16*>(smem + OFF_W3S);
#pragma unroll
            for (int it = 0; it < 8; ++it) {
                int idx = it * 512 + tid;      // 4096 float4 total
                float4 f = w3p[idx];
                int e = idx >> 6, n0 = (idx & 63) * 4;
                W3S[(n0 + 0) * 72 + e] = __float2bfloat16(f.x);
                W3S[(n0 + 1) * 72 + e] = __float2bfloat16(f.y);
                W3S[(n0 + 2) * 72 + e] = __float2bfloat16(f.z);
                W3S[(n0 + 3) * 72 + e] = __float2bfloat16(f.w);
            }
        }

        uint32_t az[4][4];
#pragma unroll
        for (int kt = 0; kt < 4; ++kt) {
            float v[2][4];
#pragma unroll
            for (int p = 0; p < 2; ++p) {
                int nt = 2 * kt + p;
                float bx = sb2[nt * 8 + 2 * q], by = sb2[nt * 8 + 2 * q + 1];
                v[p][0] = zacc[nt][0] + bx; v[p][1] = zacc[nt][1] + by;
                v[p][2] = zacc[nt][2] + bx; v[p][3] = zacc[nt][3] + by;
            }
            __nv_bfloat162 p0 = __floats2bfloat162_rn(v[0][0], v[0][1]);
            __nv_bfloat162 p1 = __floats2bfloat162_rn(v[0][2], v[0][3]);
            __nv_bfloat162 p2 = __floats2bfloat162_rn(v[1][0], v[1][1]);
            __nv_bfloat162 p3 = __floats2bfloat162_rn(v[1][2], v[1][3]);
            az[kt][0] = *reinterpret_cast<uint32_t*>(&p0);
            az[kt][1] = *reinterpret_cast<uint32_t*>(&p1);
            az[kt][2] = *reinterpret_cast<uint32_t*>(&p2);
            az[kt][3] = *reinterpret_cast<uint32_t*>(&p3);
        }

        int xv[2];
        xv[0] = x[(size_t)(w * 16 + r4) * T_ + i];
        xv[1] = x[(size_t)(w * 16 + r4 + 8) * T_ + i];

        __syncthreads();         // W3S ready

        const uint32_t w3_off = smem_u32 + OFF_W3S + brow * 144 + bcol;
        float sum[2] = {0.f, 0.f};
        float picked[2] = {0.f, 0.f};

#pragma unroll
        for (int n0 = 0; n0 < 4; ++n0) {
            float c[8][4];
#pragma unroll
            for (int nt = 0; nt < 8; ++nt)
#pragma unroll
                for (int u = 0; u < 4; ++u) c[nt][u] = 0.f;
#pragma unroll
            for (int ntp = 0; ntp < 4; ++ntp) {
#pragma unroll
                for (int kt = 0; kt < 4; ++kt) {
                    uint32_t b0, b1r, b2r, b3;
                    LDSM_X4(b0, b1r, b2r, b3,
                            w3_off + (n0 * 64 + ntp * 16) * 144 + kt * 32);
                    mma_bf16(c[2 * ntp + 0], az[kt], b0, b1r);
                    mma_bf16(c[2 * ntp + 1], az[kt], b2r, b3);
                }
            }
#pragma unroll
            for (int nt = 0; nt < 8; ++nt)
#pragma unroll
                for (int u = 0; u < 4; ++u) {
                    int n = n0 * 64 + nt * 8 + 2 * q + (u & 1);
                    int hh = u >> 1;
                    float v = c[nt][u];
                    sum[hh] += __expf(v);
                    if (n == xv[hh]) picked[hh] = v;
                }
        }

#pragma unroll
        for (int hh = 0; hh < 2; ++hh) {
            float sv = sum[hh], pv = picked[hh];
            sv += __shfl_xor_sync(0xffffffffu, sv, 1);
            sv += __shfl_xor_sync(0xffffffffu, sv, 2);
            pv += __shfl_xor_sync(0xffffffffu, pv, 1);
            pv += __shfl_xor_sync(0xffffffffu, pv, 2);
            if (q == 0) {
                int row = w * 16 + r4 + 8 * hh;
                out[(size_t)row * T_ + i] = __logf(sv) - pv;
            }
        }
        return;
    }

    // producers: join the two consumer barriers, then exit
    __syncthreads();
    __syncthreads();
}

// ---------------------------------------------------------------------------
extern "C" void kernel_launch(void* const* d_in, const int* in_sizes, int n_in,
                              void* d_out, int out_size) {
    const int*   x    = (const int*)  d_in[0];  // [B,T]
    const float* emb  = (const float*)d_in[1];  // [N*T,E]
    const float* lin1 = (const float*)d_in[2];  // [T,T,E,H]
    const float* b1   = (const float*)d_in[3];  // [T,T,H]
    const float* lin2 = (const float*)d_in[4];  // [T,(T-1)*H,E]
    const float* b2   = (const float*)d_in[5];  // [T,E]
    const float* w3   = (const float*)d_in[6];  // [T,E,N]
    float* out = (float*)d_out;                 // [B,T]

    cudaFuncSetAttribute(fused_all_kernel,
                         cudaFuncAttributeMaxDynamicSharedMemorySize,
                         SMEM_TOTAL);

    gather_frag_kernel<<<T_, 256>>>(x, emb);
    fused_all_kernel<<<T_, NTHREADS, SMEM_TOTAL>>>(lin1, b1, lin2, b2,
                                                   w3, x, out);
}